// round 7
// baseline (speedup 1.0000x reference)
#include <cuda_runtime.h>
#include <cstdint>

// Problem constants (fixed by the dataset)
#define B_    8
#define V_    12288
#define E_    98304
#define FIN_  256
#define FOUT_ 256
#define KCH_  4
#define BF_   (B_*FIN_)    // 2048 floats per node row (node-major layout)
#define ROWS_ (B_*V_)      // 98304 output rows

// ---------------- scratch (device globals: no runtime allocation) ----------
// Self-cleaning invariant: g_sum/g_sq are zero at module load and are returned
// to zero by the end of every kernel_launch call (bnfinal re-zeroes them).
__device__ float g_T1[(size_t)V_*BF_];   // T1 = L x          [V][B*Fin]
__device__ float g_T2[(size_t)V_*BF_];   // T2 = 2 L T1 - x
__device__ float g_T3[(size_t)V_*BF_];   // T3 = 2 L T2 - T1
__device__ int   g_rowptr[V_+1];
__device__ int   g_cursor[V_];
__device__ int   g_col[E_];              // src indices sorted by dst
__device__ float g_w[E_];                // weights sorted by dst
__device__ float g_sum[FOUT_], g_sq[FOUT_];
__device__ float g_scale[FOUT_], g_shift[FOUT_];

// ---------------- CSR build: fused histogram + scan (single block) ----------
// 1024 threads. Phase 1: smem histogram of edge dst (48KB, exactly static max).
// Phase 2: per-thread 12-count partial sums -> registers; scan over 1024 block
// sums reusing the same smem; write rowptr + cursor.
__global__ __launch_bounds__(1024) void k_histscan(const int* __restrict__ dst) {
    __shared__ int scnt[V_];                       // 49152 bytes
    int t = threadIdx.x;
    #pragma unroll
    for (int i = 0; i < 12; ++i) scnt[t*12 + i] = 0;
    __syncthreads();
    #pragma unroll 1
    for (int e = t; e < E_; e += 1024)
        atomicAdd(&scnt[__ldg(&dst[e])], 1);
    __syncthreads();

    int base = t*12;
    int loc[12];
    int s = 0;
    #pragma unroll
    for (int i = 0; i < 12; ++i) { loc[i] = s; s += scnt[base+i]; }
    __syncthreads();           // counts now in registers; reuse scnt for scan
    scnt[t] = s;
    __syncthreads();
    for (int off = 1; off < 1024; off <<= 1) {
        int v = 0;
        if (t >= off) v = scnt[t-off];
        __syncthreads();
        if (t >= off) scnt[t] += v;
        __syncthreads();
    }
    int pre = (t == 0) ? 0 : scnt[t-1];
    #pragma unroll
    for (int i = 0; i < 12; ++i) {
        int p = pre + loc[i];
        g_rowptr[base+i] = p;
        g_cursor[base+i] = p;
    }
    if (t == 1023) g_rowptr[V_] = scnt[1023];
}

__global__ void k_scatter(const int* __restrict__ src, const int* __restrict__ dst,
                          const float* __restrict__ ew) {
    int e = blockIdx.x*blockDim.x + threadIdx.x;
    if (e < E_) {
        int d = dst[e];
        int p = atomicAdd(&g_cursor[d], 1);
        g_col[p] = src[e];
        g_w[p]   = ew[e];
    }
}

// ---------------- SpMM: Chebyshev recursion --------------------------------
// grid (V, 2): each block covers one node x one batch-half (batches 0-3 or
// 4-7) -> 50MB gather working set, L2-resident. 256 threads x 1 float4.
// 4-edge unroll -> 4 independent gathers in flight per thread.
__device__ __forceinline__ void fma4(float4& acc, float wt, const float4& t) {
    acc.x = fmaf(wt, t.x, acc.x);
    acc.y = fmaf(wt, t.y, acc.y);
    acc.z = fmaf(wt, t.z, acc.z);
    acc.w = fmaf(wt, t.w, acc.w);
}

__global__ __launch_bounds__(256) void k_spmm(const float* __restrict__ x, int stage) {
    const float* y;  const float* p2 = nullptr;  float* o;
    long ys, ps = 0;
    const int v  = blockIdx.x;
    const int j0 = (blockIdx.y << 10) + threadIdx.x*4;   // global col 0..2047
    const long xo = (long)(j0>>8)*((long)V_*FIN_) + (j0&255);
    long yo, po = 0;
    if (stage == 1)      { y = x;    ys = FIN_; yo = xo; o = g_T1; }
    else if (stage == 2) { y = g_T1; ys = BF_;  yo = j0;
                           p2 = x;   ps = FIN_; po = xo; o = g_T2; }
    else                 { y = g_T2; ys = BF_;  yo = j0;
                           p2 = g_T1; ps = BF_; po = j0; o = g_T3; }

    int r0 = g_rowptr[v], r1 = g_rowptr[v+1];
    float4 a0 = make_float4(0,0,0,0);

    int e = r0;
    #pragma unroll 1
    for (; e + 4 <= r1; e += 4) {
        int   s0 = __ldg(&g_col[e]),   s1 = __ldg(&g_col[e+1]);
        int   s2 = __ldg(&g_col[e+2]), s3 = __ldg(&g_col[e+3]);
        float w0 = __ldg(&g_w[e]),     w1 = __ldg(&g_w[e+1]);
        float w2 = __ldg(&g_w[e+2]),   w3 = __ldg(&g_w[e+3]);
        float4 t0 = *(const float4*)(y + yo + (long)s0*ys);
        float4 t1 = *(const float4*)(y + yo + (long)s1*ys);
        float4 t2 = *(const float4*)(y + yo + (long)s2*ys);
        float4 t3 = *(const float4*)(y + yo + (long)s3*ys);
        fma4(a0, w0, t0);
        fma4(a0, w1, t1);
        fma4(a0, w2, t2);
        fma4(a0, w3, t3);
    }
    #pragma unroll 1
    for (; e < r1; ++e) {
        int   s0 = __ldg(&g_col[e]);
        float w0 = __ldg(&g_w[e]);
        float4 t0 = *(const float4*)(y + yo + (long)s0*ys);
        fma4(a0, w0, t0);
    }
    if (p2) {
        float4 t0 = *(const float4*)(p2 + po + (long)v*ps);
        a0.x = 2.f*a0.x - t0.x; a0.y = 2.f*a0.y - t0.y;
        a0.z = 2.f*a0.z - t0.z; a0.w = 2.f*a0.w - t0.w;
    }
    *(float4*)(o + (long)v*BF_ + j0) = a0;
}

// ---------------- TF32 tensor-core GEMM (double-buffered, fused BN stats) ---
// out[b,v,o] = sum_p sum_i A_p(v,b,i) * W[p,i,o]
// A_0 = x (layout [B][V][Fin]); A_1..3 = g_T1..3 (layout [V][B*Fin])
// Bias omitted: constant per-channel shift cancels through BN mean subtraction.
// R3-proven config: BM=BN=128, BK=16, no occupancy cap. UNCHANGED this round
// for clean profile attribution (gemm is now launch index 5 = ncu capture).
#define BM 128
#define BN 128
#define BK 16
#define NTILES (KCH_ * FIN_ / BK)   // 64

__device__ __forceinline__ uint32_t f2tf(float f) {
    uint32_t u;
    asm("cvt.rna.tf32.f32 %0, %1;" : "=r"(u) : "f"(f));
    return u;
}

__global__ __launch_bounds__(256) void k_gemm(const float* __restrict__ x,
                                              const float* __restrict__ w,
                                              float* __restrict__ out) {
    __shared__ uint32_t As[2][BK][BM+4];
    __shared__ uint32_t Bs[2][BK][BN+4];
    __shared__ float s_s[BN], s_q[BN];

    const int b      = blockIdx.z;
    const int nbase0 = blockIdx.x * BN;   // N split in x -> neighbors share A tile (L2)
    const int vbase  = blockIdx.y * BM;
    const int tid  = threadIdx.x;
    const int lane = tid & 31, warp = tid >> 5;
    const int wm = warp & 3, wn = warp >> 2;
    const int g = lane >> 2, tg = lane & 3;
    const int a_c = tid & 3,  a_m  = tid >> 2;   // A: k-quad, row (and row+64)
    const int b_n4 = tid & 31, b_k = tid >> 5;   // B: float4 col, k row (and +8)

    if (tid < BN) { s_s[tid] = 0.f; s_q[tid] = 0.f; }

    float acc[2][8][4];
    #pragma unroll
    for (int i = 0; i < 2; ++i)
        #pragma unroll
        for (int j = 0; j < 8; ++j)
            #pragma unroll
            for (int c = 0; c < 4; ++c) acc[i][j][c] = 0.f;

    float4 ra[2], rb[2];

    // tile prefetch (global -> regs)
    auto prefetch = [&](int t) {
        int p  = t >> 4;
        int kb = (t & 15) * BK;
        const float* abase; long astride;
        if (p == 0)      { abase = x    + (long)b*V_*FIN_; astride = FIN_; }
        else if (p == 1) { abase = g_T1 + (long)b*FIN_;    astride = BF_;  }
        else if (p == 2) { abase = g_T2 + (long)b*FIN_;    astride = BF_;  }
        else             { abase = g_T3 + (long)b*FIN_;    astride = BF_;  }
        const float* wp = w + (long)p*FIN_*FOUT_ + nbase0;
        ra[0] = *(const float4*)(abase + (long)(vbase + a_m     )*astride + kb + a_c*4);
        ra[1] = *(const float4*)(abase + (long)(vbase + a_m + 64)*astride + kb + a_c*4);
        rb[0] = *(const float4*)(wp + (long)(kb + b_k    )*FOUT_ + b_n4*4);
        rb[1] = *(const float4*)(wp + (long)(kb + b_k + 8)*FOUT_ + b_n4*4);
    };

    prefetch(0);
    int cur = 0;
    #pragma unroll 1
    for (int t = 0; t < NTILES; ++t) {
        // store regs -> smem[cur] (convert to tf32 here, off the load path)
        As[cur][a_c*4+0][a_m] = f2tf(ra[0].x);
        As[cur][a_c*4+1][a_m] = f2tf(ra[0].y);
        As[cur][a_c*4+2][a_m] = f2tf(ra[0].z);
        As[cur][a_c*4+3][a_m] = f2tf(ra[0].w);
        As[cur][a_c*4+0][a_m+64] = f2tf(ra[1].x);
        As[cur][a_c*4+1][a_m+64] = f2tf(ra[1].y);
        As[cur][a_c*4+2][a_m+64] = f2tf(ra[1].z);
        As[cur][a_c*4+3][a_m+64] = f2tf(ra[1].w);
        {
            uint32_t* d0 = &Bs[cur][b_k    ][b_n4*4];
            uint32_t* d1 = &Bs[cur][b_k + 8][b_n4*4];
            d0[0] = f2tf(rb[0].x); d0[1] = f2tf(rb[0].y);
            d0[2] = f2tf(rb[0].z); d0[3] = f2tf(rb[0].w);
            d1[0] = f2tf(rb[1].x); d1[1] = f2tf(rb[1].y);
            d1[2] = f2tf(rb[1].z); d1[3] = f2tf(rb[1].w);
        }
        __syncthreads();
        if (t + 1 < NTILES) prefetch(t + 1);   // overlap global loads with mma

        #pragma unroll
        for (int kk = 0; kk < BK; kk += 8) {
            uint32_t a[2][4];
            #pragma unroll
            for (int mt = 0; mt < 2; ++mt) {
                int mb = wm*32 + mt*16;
                a[mt][0] = As[cur][kk+tg  ][mb+g  ];
                a[mt][1] = As[cur][kk+tg  ][mb+g+8];
                a[mt][2] = As[cur][kk+tg+4][mb+g  ];
                a[mt][3] = As[cur][kk+tg+4][mb+g+8];
            }
            #pragma unroll
            for (int nt = 0; nt < 8; ++nt) {
                int nb = wn*64 + nt*8;
                uint32_t b0 = Bs[cur][kk+tg  ][nb+g];
                uint32_t b1 = Bs[cur][kk+tg+4][nb+g];
                #pragma unroll
                for (int mt = 0; mt < 2; ++mt) {
                    asm volatile(
                        "mma.sync.aligned.m16n8k8.row.col.f32.tf32.tf32.f32 "
                        "{%0,%1,%2,%3}, {%4,%5,%6,%7}, {%8,%9}, {%0,%1,%2,%3};\n"
                        : "+f"(acc[mt][nt][0]), "+f"(acc[mt][nt][1]),
                          "+f"(acc[mt][nt][2]), "+f"(acc[mt][nt][3])
                        : "r"(a[mt][0]), "r"(a[mt][1]),
                          "r"(a[mt][2]), "r"(a[mt][3]),
                          "r"(b0), "r"(b1));
                }
            }
        }
        cur ^= 1;
    }

    // epilogue: write raw (pre-BN) result
    #pragma unroll
    for (int mt = 0; mt < 2; ++mt) {
        int row0 = vbase + wm*32 + mt*16 + g;
        #pragma unroll
        for (int nt = 0; nt < 8; ++nt) {
            int col = nbase0 + wn*64 + nt*8 + tg*2;
            float2* p0 = (float2*)&out[((long)b*V_ + row0    )*FOUT_ + col];
            float2* p1 = (float2*)&out[((long)b*V_ + row0 + 8)*FOUT_ + col];
            *p0 = make_float2(acc[mt][nt][0], acc[mt][nt][1]);
            *p1 = make_float2(acc[mt][nt][2], acc[mt][nt][3]);
        }
    }

    // fused BN stats: per-column sum / sumsq over this block's 128 rows
    #pragma unroll
    for (int nt = 0; nt < 8; ++nt) {
        float s0 = acc[0][nt][0] + acc[0][nt][2] + acc[1][nt][0] + acc[1][nt][2];
        float s1 = acc[0][nt][1] + acc[0][nt][3] + acc[1][nt][1] + acc[1][nt][3];
        float q0 = acc[0][nt][0]*acc[0][nt][0] + acc[0][nt][2]*acc[0][nt][2]
                 + acc[1][nt][0]*acc[1][nt][0] + acc[1][nt][2]*acc[1][nt][2];
        float q1 = acc[0][nt][1]*acc[0][nt][1] + acc[0][nt][3]*acc[0][nt][3]
                 + acc[1][nt][1]*acc[1][nt][1] + acc[1][nt][3]*acc[1][nt][3];
        #pragma unroll
        for (int m = 4; m <= 16; m <<= 1) {
            s0 += __shfl_xor_sync(0xffffffffu, s0, m);
            s1 += __shfl_xor_sync(0xffffffffu, s1, m);
            q0 += __shfl_xor_sync(0xffffffffu, q0, m);
            q1 += __shfl_xor_sync(0xffffffffu, q1, m);
        }
        if (lane < 4) {
            int colr = wn*64 + nt*8 + tg*2;
            atomicAdd(&s_s[colr  ], s0); atomicAdd(&s_q[colr  ], q0);
            atomicAdd(&s_s[colr+1], s1); atomicAdd(&s_q[colr+1], q1);
        }
    }
    __syncthreads();
    if (tid < BN) {
        atomicAdd(&g_sum[nbase0 + tid], s_s[tid]);
        atomicAdd(&g_sq[nbase0 + tid],  s_q[tid]);
    }
}

// ---------------- BatchNorm finalize + apply + ReLU -------------------------
__global__ void k_bnfinal(const float* __restrict__ gamma,
                          const float* __restrict__ beta) {
    int o = threadIdx.x;
    const float n = (float)ROWS_;
    float mean = g_sum[o] / n;
    float var  = g_sq[o] / n - mean*mean;      // biased variance (torch-style)
    float sc   = gamma[o] * rsqrtf(var + 1e-5f);
    g_scale[o] = sc;
    g_shift[o] = beta[o] - mean*sc;
    g_sum[o] = 0.f;                 // self-clean for next call
    g_sq[o]  = 0.f;
}

__global__ __launch_bounds__(256) void k_bnapply(float* __restrict__ out) {
    long i = ((long)blockIdx.x*blockDim.x + threadIdx.x) * 4;
    float4 v = *(float4*)(out + i);
    int o = (int)(i & 255);
    v.x = fmaxf(fmaf(v.x, g_scale[o  ], g_shift[o  ]), 0.f);
    v.y = fmaxf(fmaf(v.y, g_scale[o+1], g_shift[o+1]), 0.f);
    v.z = fmaxf(fmaf(v.z, g_scale[o+2], g_shift[o+2]), 0.f);
    v.w = fmaxf(fmaf(v.w, g_scale[o+3], g_shift[o+3]), 0.f);
    *(float4*)(out + i) = v;
}

// ---------------- launch -----------------------------------------------------
extern "C" void kernel_launch(void* const* d_in, const int* in_sizes, int n_in,
                              void* d_out, int out_size) {
    const float* x     = (const float*)d_in[0];
    const float* ew    = (const float*)d_in[1];
    const float* w     = (const float*)d_in[2];
    const float* bias  = (const float*)d_in[3]; (void)bias; // cancels under BN
    const float* gamma = (const float*)d_in[4];
    const float* beta  = (const float*)d_in[5];
    const int*   esrc  = (const int*)d_in[6];
    const int*   edst  = (const int*)d_in[7];
    float* out = (float*)d_out;
    (void)in_sizes; (void)n_in; (void)out_size;

    // CSR build (by dst): fused hist+scan (launch 0), scatter (launch 1)
    k_histscan<<<1, 1024>>>(edst);
    k_scatter<<<E_/256, 256>>>(esrc, edst, ew);

    // Chebyshev recursion (launches 2,3,4)
    dim3 gs(V_, 2);
    k_spmm<<<gs, 256>>>(x, 1);
    k_spmm<<<gs, 256>>>(x, 2);
    k_spmm<<<gs, 256>>>(x, 3);

    // TF32 GEMM -> raw output + fused BN statistics (launch 5 = ncu capture)
    dim3 gg(FOUT_/BN, V_/BM, B_);
    k_gemm<<<gg, 256>>>(x, w, out);

    // BatchNorm finalize + apply + ReLU
    k_bnfinal<<<1, FOUT_>>>(gamma, beta);
    k_bnapply<<<(ROWS_*FOUT_)/4/256, 256>>>(out);
}

// round 9
// speedup vs baseline: 1.3385x; 1.3385x over previous
#include <cuda_runtime.h>
#include <cuda_fp16.h>
#include <cstdint>

// Problem constants (fixed by the dataset)
#define B_    8
#define V_    12288
#define E_    98304
#define FIN_  256
#define FOUT_ 256
#define KCH_  4
#define BF_   (B_*FIN_)    // 2048 floats per node row
#define ROWS_ (B_*V_)      // 98304 output rows

// ---------------- scratch (device globals: no runtime allocation) ----------
// Self-cleaning invariant: g_cnt, g_sum, g_sq are zero at module load and are
// returned to zero by the end of every kernel_launch call.
__device__ float g_T1[(size_t)V_*BF_];
__device__ float g_T2[(size_t)V_*BF_];
__device__ float g_T3[(size_t)V_*BF_];
__device__ int   g_rowptr[V_+1];
__device__ int   g_cursor[V_];
__device__ int   g_cnt[V_];
__device__ int   g_col[E_];
__device__ float g_w[E_];
__device__ float g_sum[FOUT_], g_sq[FOUT_];
__device__ float g_scale[FOUT_], g_shift[FOUT_];

// ---------------- CSR build (R6-proven) --------------------------------------
__global__ void k_hist(const int* __restrict__ dst) {
    int e = blockIdx.x*blockDim.x + threadIdx.x;
    if (e < E_) atomicAdd(&g_cnt[dst[e]], 1);
}

__global__ void k_scan() {
    __shared__ int sh[1024];
    int t = threadIdx.x;
    int base = t*12;
    int loc[12];
    int s = 0;
    #pragma unroll
    for (int i = 0; i < 12; ++i) { loc[i] = s; s += g_cnt[base+i]; }
    sh[t] = s;
    __syncthreads();
    for (int off = 1; off < 1024; off <<= 1) {
        int v = 0;
        if (t >= off) v = sh[t-off];
        __syncthreads();
        if (t >= off) sh[t] += v;
        __syncthreads();
    }
    int pre = (t == 0) ? 0 : sh[t-1];
    #pragma unroll
    for (int i = 0; i < 12; ++i) {
        int p = pre + loc[i];
        g_rowptr[base+i] = p;
        g_cursor[base+i] = p;
    }
    if (t == 1023) g_rowptr[V_] = sh[1023];
}

__global__ void k_scatter(const int* __restrict__ src, const int* __restrict__ dst,
                          const float* __restrict__ ew) {
    int e = blockIdx.x*blockDim.x + threadIdx.x;
    if (e < E_) {
        int d = dst[e];
        int p = atomicAdd(&g_cursor[d], 1);
        g_col[p] = src[e];
        g_w[p]   = ew[e];
        atomicSub(&g_cnt[d], 1);   // self-clean for next call
    }
}

// ---------------- SpMM: Chebyshev recursion (R6-proven) ----------------------
__device__ __forceinline__ void fma4(float4& acc, float wt, const float4& t) {
    acc.x = fmaf(wt, t.x, acc.x);
    acc.y = fmaf(wt, t.y, acc.y);
    acc.z = fmaf(wt, t.z, acc.z);
    acc.w = fmaf(wt, t.w, acc.w);
}

__global__ __launch_bounds__(256) void k_spmm(const float* __restrict__ x, int stage) {
    const float* y;  const float* p2 = nullptr;  float* o;
    long ys, ps = 0;
    const int v  = blockIdx.x;
    const int j0 = (blockIdx.y << 10) + threadIdx.x*4;
    const long xo = (long)(j0>>8)*((long)V_*FIN_) + (j0&255);
    long yo, po = 0;
    if (stage == 1)      { y = x;    ys = FIN_; yo = xo; o = g_T1; }
    else if (stage == 2) { y = g_T1; ys = BF_;  yo = j0;
                           p2 = x;   ps = FIN_; po = xo; o = g_T2; }
    else                 { y = g_T2; ys = BF_;  yo = j0;
                           p2 = g_T1; ps = BF_; po = j0; o = g_T3; }

    int r0 = g_rowptr[v], r1 = g_rowptr[v+1];
    float4 a0 = make_float4(0,0,0,0);

    int e = r0;
    #pragma unroll 1
    for (; e + 4 <= r1; e += 4) {
        int   s0 = __ldg(&g_col[e]),   s1 = __ldg(&g_col[e+1]);
        int   s2 = __ldg(&g_col[e+2]), s3 = __ldg(&g_col[e+3]);
        float w0 = __ldg(&g_w[e]),     w1 = __ldg(&g_w[e+1]);
        float w2 = __ldg(&g_w[e+2]),   w3 = __ldg(&g_w[e+3]);
        float4 t0 = *(const float4*)(y + yo + (long)s0*ys);
        float4 t1 = *(const float4*)(y + yo + (long)s1*ys);
        float4 t2 = *(const float4*)(y + yo + (long)s2*ys);
        float4 t3 = *(const float4*)(y + yo + (long)s3*ys);
        fma4(a0, w0, t0);
        fma4(a0, w1, t1);
        fma4(a0, w2, t2);
        fma4(a0, w3, t3);
    }
    #pragma unroll 1
    for (; e < r1; ++e) {
        int   s0 = __ldg(&g_col[e]);
        float w0 = __ldg(&g_w[e]);
        float4 t0 = *(const float4*)(y + yo + (long)s0*ys);
        fma4(a0, w0, t0);
    }
    if (p2) {
        float4 t0 = *(const float4*)(p2 + po + (long)v*ps);
        a0.x = 2.f*a0.x - t0.x; a0.y = 2.f*a0.y - t0.y;
        a0.z = 2.f*a0.z - t0.z; a0.w = 2.f*a0.w - t0.w;
    }
    *(float4*)(o + (long)v*BF_ + j0) = a0;
}

// ---------------- FP16 tensor-core GEMM (m16n8k16, fused BN stats) ----------
// out[b,v,o] = sum_p sum_i A_p(v,b,i) * W[p,i,o]
// fp16 inputs (rn from f32; same 10+1-bit mantissa as tf32), fp32 accumulate.
// BM=64, BN=256 (full FOUT -> A read from HBM exactly once), BK=32.
// Bias omitted: constant per-channel shift cancels through BN mean subtraction.
#define BM 64
#define BN 256
#define BK 32
#define NCH (KCH_ * FIN_ / BK)   // 32 chunks

__device__ __forceinline__ uint32_t h2u(__half2 h) {
    return *reinterpret_cast<uint32_t*>(&h);
}

__global__ __launch_bounds__(256) void k_gemm(const float* __restrict__ x,
                                              const float* __restrict__ w,
                                              float* __restrict__ out) {
    // half2 tiles, k-pair-major: As[k2][m] = (k=2*k2, 2*k2+1) of row m
    __shared__ uint32_t As[2][16][BM+4];    //  8704 B
    __shared__ uint32_t Bs[2][16][BN+8];    // 33792 B (row stride 16B-aligned)
    __shared__ float s_s[BN], s_q[BN];      //  2048 B

    const int b     = blockIdx.y;
    const int vbase = blockIdx.x * BM;
    const int tid  = threadIdx.x;
    const int lane = tid & 31, warp = tid >> 5;
    const int wm = warp & 1, wn = warp >> 1;   // 2 warps along M, 4 along N
    const int g = lane >> 2, tg = lane & 3;

    s_s[tid] = 0.f; s_q[tid] = 0.f;

    float acc[2][8][4];
    #pragma unroll
    for (int i = 0; i < 2; ++i)
        #pragma unroll
        for (int j = 0; j < 8; ++j)
            #pragma unroll
            for (int c = 0; c < 4; ++c) acc[i][j][c] = 0.f;

    // prefetch registers (already converted to half2)
    uint32_t pa[2][2];      // 2 A items x (h01, h23)
    uint32_t pb[4][4];      // 4 B items x 4 half2 (k-pairs for n..n+3)

    auto prefetch = [&](int t) {
        const int p  = t >> 3;
        const int kb = (t & 7) * BK;
        const float* ab; long as_;
        if (p == 0)      { ab = x    + (long)b*V_*FIN_; as_ = FIN_; }
        else if (p == 1) { ab = g_T1 + (long)b*FIN_;    as_ = BF_;  }
        else if (p == 2) { ab = g_T2 + (long)b*FIN_;    as_ = BF_;  }
        else             { ab = g_T3 + (long)b*FIN_;    as_ = BF_;  }
        #pragma unroll
        for (int i = 0; i < 2; ++i) {
            int item = tid + i*256;            // 0..511
            int row = item >> 3, q = item & 7;
            float4 v = *(const float4*)(ab + (long)(vbase+row)*as_ + kb + q*4);
            pa[i][0] = h2u(__floats2half2_rn(v.x, v.y));
            pa[i][1] = h2u(__floats2half2_rn(v.z, v.w));
        }
        const float* wb = w + (long)p*FIN_*FOUT_ + (long)kb*FOUT_;
        #pragma unroll
        for (int i = 0; i < 4; ++i) {
            int item = tid + i*256;            // 0..1023
            int pk = item >> 6, n4 = item & 63;
            float4 v0 = *(const float4*)(wb + (long)(2*pk  )*FOUT_ + n4*4);
            float4 v1 = *(const float4*)(wb + (long)(2*pk+1)*FOUT_ + n4*4);
            pb[i][0] = h2u(__floats2half2_rn(v0.x, v1.x));
            pb[i][1] = h2u(__floats2half2_rn(v0.y, v1.y));
            pb[i][2] = h2u(__floats2half2_rn(v0.z, v1.z));
            pb[i][3] = h2u(__floats2half2_rn(v0.w, v1.w));
        }
    };

    prefetch(0);
    int cur = 0;
    #pragma unroll 1
    for (int t = 0; t < NCH; ++t) {
        // store prefetched regs -> smem[cur]
        #pragma unroll
        for (int i = 0; i < 2; ++i) {
            int item = tid + i*256;
            int row = item >> 3, q = item & 7;
            As[cur][2*q  ][row] = pa[i][0];
            As[cur][2*q+1][row] = pa[i][1];
        }
        #pragma unroll
        for (int i = 0; i < 4; ++i) {
            int item = tid + i*256;
            int pk = item >> 6, n4 = item & 63;
            *(uint4*)&Bs[cur][pk][n4*4] =
                make_uint4(pb[i][0], pb[i][1], pb[i][2], pb[i][3]);
        }
        __syncthreads();
        if (t + 1 < NCH) prefetch(t + 1);   // overlap global loads with mma

        #pragma unroll
        for (int kk2 = 0; kk2 < 16; kk2 += 8) {   // two k16 steps
            uint32_t a[2][4];
            #pragma unroll
            for (int mt = 0; mt < 2; ++mt) {
                int mb = wm*32 + mt*16;
                a[mt][0] = As[cur][kk2+tg  ][mb+g  ];
                a[mt][1] = As[cur][kk2+tg  ][mb+g+8];
                a[mt][2] = As[cur][kk2+tg+4][mb+g  ];
                a[mt][3] = As[cur][kk2+tg+4][mb+g+8];
            }
            #pragma unroll
            for (int nt = 0; nt < 8; ++nt) {
                int nb = wn*64 + nt*8;
                uint32_t b0 = Bs[cur][kk2+tg  ][nb+g];
                uint32_t b1 = Bs[cur][kk2+tg+4][nb+g];
                #pragma unroll
                for (int mt = 0; mt < 2; ++mt) {
                    asm volatile(
                        "mma.sync.aligned.m16n8k16.row.col.f32.f16.f16.f32 "
                        "{%0,%1,%2,%3}, {%4,%5,%6,%7}, {%8,%9}, {%0,%1,%2,%3};\n"
                        : "+f"(acc[mt][nt][0]), "+f"(acc[mt][nt][1]),
                          "+f"(acc[mt][nt][2]), "+f"(acc[mt][nt][3])
                        : "r"(a[mt][0]), "r"(a[mt][1]),
                          "r"(a[mt][2]), "r"(a[mt][3]),
                          "r"(b0), "r"(b1));
                }
            }
        }
        cur ^= 1;
    }

    // epilogue: write raw (pre-BN) result
    #pragma unroll
    for (int mt = 0; mt < 2; ++mt) {
        int row0 = vbase + wm*32 + mt*16 + g;
        #pragma unroll
        for (int nt = 0; nt < 8; ++nt) {
            int col = wn*64 + nt*8 + tg*2;
            float2* p0 = (float2*)&out[((long)b*V_ + row0    )*FOUT_ + col];
            float2* p1 = (float2*)&out[((long)b*V_ + row0 + 8)*FOUT_ + col];
            *p0 = make_float2(acc[mt][nt][0], acc[mt][nt][1]);
            *p1 = make_float2(acc[mt][nt][2], acc[mt][nt][3]);
        }
    }

    // fused BN stats: per-column sum / sumsq over this block's 64 rows
    #pragma unroll
    for (int nt = 0; nt < 8; ++nt) {
        float s0 = acc[0][nt][0] + acc[0][nt][2] + acc[1][nt][0] + acc[1][nt][2];
        float s1 = acc[0][nt][1] + acc[0][nt][3] + acc[1][nt][1] + acc[1][nt][3];
        float q0 = acc[0][nt][0]*acc[0][nt][0] + acc[0][nt][2]*acc[0][nt][2]
                 + acc[1][nt][0]*acc[1][nt][0] + acc[1][nt][2]*acc[1][nt][2];
        float q1 = acc[0][nt][1]*acc[0][nt][1] + acc[0][nt][3]*acc[0][nt][3]
                 + acc[1][nt][1]*acc[1][nt][1] + acc[1][nt][3]*acc[1][nt][3];
        #pragma unroll
        for (int m = 4; m <= 16; m <<= 1) {
            s0 += __shfl_xor_sync(0xffffffffu, s0, m);
            s1 += __shfl_xor_sync(0xffffffffu, s1, m);
            q0 += __shfl_xor_sync(0xffffffffu, q0, m);
            q1 += __shfl_xor_sync(0xffffffffu, q1, m);
        }
        if (lane < 4) {
            int colr = wn*64 + nt*8 + tg*2;
            atomicAdd(&s_s[colr  ], s0); atomicAdd(&s_q[colr  ], q0);
            atomicAdd(&s_s[colr+1], s1); atomicAdd(&s_q[colr+1], q1);
        }
    }
    __syncthreads();
    atomicAdd(&g_sum[tid], s_s[tid]);
    atomicAdd(&g_sq[tid],  s_q[tid]);
}

// ---------------- BatchNorm finalize + apply + ReLU -------------------------
__global__ void k_bnfinal(const float* __restrict__ gamma,
                          const float* __restrict__ beta) {
    int o = threadIdx.x;
    const float n = (float)ROWS_;
    float mean = g_sum[o] / n;
    float var  = g_sq[o] / n - mean*mean;      // biased variance (torch-style)
    float sc   = gamma[o] * rsqrtf(var + 1e-5f);
    g_scale[o] = sc;
    g_shift[o] = beta[o] - mean*sc;
    g_sum[o] = 0.f;                 // self-clean for next call
    g_sq[o]  = 0.f;
}

__global__ __launch_bounds__(256) void k_bnapply(float* __restrict__ out) {
    long i = ((long)blockIdx.x*blockDim.x + threadIdx.x) * 4;
    float4 v = *(float4*)(out + i);
    int o = (int)(i & 255);
    v.x = fmaxf(fmaf(v.x, g_scale[o  ], g_shift[o  ]), 0.f);
    v.y = fmaxf(fmaf(v.y, g_scale[o+1], g_shift[o+1]), 0.f);
    v.z = fmaxf(fmaf(v.z, g_scale[o+2], g_shift[o+2]), 0.f);
    v.w = fmaxf(fmaf(v.w, g_scale[o+3], g_shift[o+3]), 0.f);
    *(float4*)(out + i) = v;
}

// ---------------- launch -----------------------------------------------------
extern "C" void kernel_launch(void* const* d_in, const int* in_sizes, int n_in,
                              void* d_out, int out_size) {
    const float* x     = (const float*)d_in[0];
    const float* ew    = (const float*)d_in[1];
    const float* w     = (const float*)d_in[2];
    const float* bias  = (const float*)d_in[3]; (void)bias; // cancels under BN
    const float* gamma = (const float*)d_in[4];
    const float* beta  = (const float*)d_in[5];
    const int*   esrc  = (const int*)d_in[6];
    const int*   edst  = (const int*)d_in[7];
    float* out = (float*)d_out;
    (void)in_sizes; (void)n_in; (void)out_size;

    // CSR build (g_cnt zero by static init + self-clean)
    k_hist<<<E_/256, 256>>>(edst);
    k_scan<<<1, 1024>>>();
    k_scatter<<<E_/256, 256>>>(esrc, edst, ew);

    // Chebyshev recursion (batch-halved for L2 residency)
    dim3 gs(V_, 2);
    k_spmm<<<gs, 256>>>(x, 1);
    k_spmm<<<gs, 256>>>(x, 2);
    k_spmm<<<gs, 256>>>(x, 3);

    // FP16 tensor-core GEMM -> raw output + fused BN statistics
    dim3 gg(V_/BM, B_);
    k_gemm<<<gg, 256>>>(x, w, out);

    // BatchNorm finalize + apply + ReLU
    k_bnfinal<<<1, FOUT_>>>(gamma, beta);
    k_bnapply<<<(ROWS_*FOUT_)/4/256, 256>>>(out);
}